// round 3
// baseline (speedup 1.0000x reference)
#include <cuda_runtime.h>
#include <cuda_bf16.h>

#define G 4
#define THREADS 256
#define NBLK (8192 / G)

// Binarized weights (written by binarize_kernel, read by fused_kernel).
// FC weights stored TRANSPOSED: [K][N] so fc inner loops read coalesced.
__device__ float g_w1b[6 * 3 * 5 * 5];      // [O][I][5][5]
__device__ float g_w2b[16 * 6 * 5 * 5];     // [O][I][5][5]
__device__ float g_fw1t[400 * 120];         // [k][j]
__device__ float g_fw2t[120 * 84];          // [k][j]
__device__ float g_fw3t[84 * 10];           // [k][j]

// One block per tensor: scale = mean(|w|), write sign(w)*scale (transposed for FCs).
__global__ void binarize_kernel(const float* __restrict__ w1,
                                const float* __restrict__ w2,
                                const float* __restrict__ fw1,
                                const float* __restrict__ fw2,
                                const float* __restrict__ fw3) {
    __shared__ float red[256];
    int t = threadIdx.x;
    const float* src = nullptr;
    float* dst = nullptr;
    int n = 0, rows = 0, cols = 0, transpose = 0;
    switch (blockIdx.x) {
        case 0: src = w1;  dst = g_w1b;  n = 450;   transpose = 0; break;
        case 1: src = w2;  dst = g_w2b;  n = 2400;  transpose = 0; break;
        case 2: src = fw1; dst = g_fw1t; n = 48000; transpose = 1; rows = 120; cols = 400; break;
        case 3: src = fw2; dst = g_fw2t; n = 10080; transpose = 1; rows = 84;  cols = 120; break;
        case 4: src = fw3; dst = g_fw3t; n = 840;   transpose = 1; rows = 10;  cols = 84;  break;
    }
    float s = 0.0f;
    for (int i = t; i < n; i += 256) s += fabsf(src[i]);
    red[t] = s;
    __syncthreads();
    for (int o = 128; o > 0; o >>= 1) {
        if (t < o) red[t] += red[t + o];
        __syncthreads();
    }
    float scale = red[0] / (float)n;
    if (!transpose) {
        for (int i = t; i < n; i += 256)
            dst[i] = (src[i] >= 0.0f) ? scale : -scale;
    } else {
        for (int i = t; i < n; i += 256) {
            int r = i / cols, c = i % cols;         // src[r][c] = w[j][k]
            dst[c * rows + r] = (src[i] >= 0.0f) ? scale : -scale;
        }
    }
}

// Fully fused forward: conv1+relu+pool -> conv2+relu+pool -> fc1 -> fc2 -> fc3.
// One CTA handles G images entirely in shared memory.
extern __shared__ float smem[];

__global__ void __launch_bounds__(THREADS, 2)
fused_kernel(const float* __restrict__ x,
             const float* __restrict__ b1, const float* __restrict__ b2,
             const float* __restrict__ fb1, const float* __restrict__ fb2,
             const float* __restrict__ fb3,
             float* __restrict__ out) {
    // smem partition (floats)
    float* const sIn = smem;                   // G*3*32*32 = G*3072
    float* const p1  = sIn + G * 3072;         // G*6*14*14 = G*1176
    float* const h2  = p1 + G * 1176;          // G*400
    float* const a1  = h2 + G * 400;           // G*120
    float* const a2  = a1 + G * 120;           // G*84
    float* const w1s = a2 + G * 84;            // 450
    float* const w2s = w1s + 450;              // 2400
    float* const b1s = w2s + 2400;             // 6
    float* const b2s = b1s + 6;                // 16

    const int tid = threadIdx.x;
    const int img0 = blockIdx.x * G;

    // ---- load inputs + weights into smem ----
    {
        const float4* xin = (const float4*)(x + (size_t)img0 * 3072);
        float4* s4 = (float4*)sIn;
        for (int i = tid; i < G * 768; i += THREADS) s4[i] = xin[i];
    }
    for (int i = tid; i < 450; i += THREADS)  w1s[i] = g_w1b[i];
    for (int i = tid; i < 2400; i += THREADS) w2s[i] = g_w2b[i];
    if (tid < 6)  b1s[tid] = b1[tid];
    if (tid < 16) b2s[tid] = b2[tid];
    __syncthreads();

    // ---- conv1 (3->6, 5x5) + relu + maxpool2 : out p1[g][c][14][14] ----
    // task = (g, pooled pixel). 6x6 input window in regs shared across 6 out
    // channels and the 2x2 pool quad.
    for (int s = tid; s < G * 196; s += THREADS) {
        int g = s / 196, p = s % 196;
        int py = p / 14, px = p % 14;
        const float* inb = sIn + g * 3072 + (py * 2) * 32 + px * 2;
        float acc[6][4];
        #pragma unroll
        for (int c = 0; c < 6; c++) {
            acc[c][0] = acc[c][1] = acc[c][2] = acc[c][3] = 0.0f;
        }
        for (int cin = 0; cin < 3; cin++) {
            float win[6][6];
            const float* ib = inb + cin * 1024;
            #pragma unroll
            for (int r = 0; r < 6; r++)
                #pragma unroll
                for (int cc = 0; cc < 6; cc++) win[r][cc] = ib[r * 32 + cc];
            #pragma unroll
            for (int c = 0; c < 6; c++) {
                const float* wb = w1s + (c * 3 + cin) * 25;
                #pragma unroll
                for (int ky = 0; ky < 5; ky++)
                    #pragma unroll
                    for (int kx = 0; kx < 5; kx++) {
                        float w = wb[ky * 5 + kx];
                        acc[c][0] = fmaf(w, win[ky][kx],         acc[c][0]);
                        acc[c][1] = fmaf(w, win[ky][kx + 1],     acc[c][1]);
                        acc[c][2] = fmaf(w, win[ky + 1][kx],     acc[c][2]);
                        acc[c][3] = fmaf(w, win[ky + 1][kx + 1], acc[c][3]);
                    }
            }
        }
        #pragma unroll
        for (int c = 0; c < 6; c++) {
            float m = fmaxf(fmaxf(acc[c][0], acc[c][1]), fmaxf(acc[c][2], acc[c][3]));
            p1[(g * 6 + c) * 196 + p] = fmaxf(m + b1s[c], 0.0f);
        }
    }
    __syncthreads();

    // ---- conv2 (6->16, 5x5) + relu + maxpool2 : out h2[g][400] ----
    // task = (g, pooled pixel, 4-channel quad)
    for (int s = tid; s < G * 100; s += THREADS) {
        int g = s / 100, r = s % 100;
        int cq = r / 25, p = r % 25;
        int py = p / 5, px = p % 5;
        const float* inb = p1 + g * 1176 + (py * 2) * 14 + px * 2;
        float acc[4][4];
        #pragma unroll
        for (int c = 0; c < 4; c++) {
            acc[c][0] = acc[c][1] = acc[c][2] = acc[c][3] = 0.0f;
        }
        for (int cin = 0; cin < 6; cin++) {
            float win[6][6];
            const float* ib = inb + cin * 196;
            #pragma unroll
            for (int rr = 0; rr < 6; rr++)
                #pragma unroll
                for (int cc = 0; cc < 6; cc++) win[rr][cc] = ib[rr * 14 + cc];
            #pragma unroll
            for (int c = 0; c < 4; c++) {
                int co = cq * 4 + c;
                const float* wb = w2s + (co * 6 + cin) * 25;
                #pragma unroll
                for (int ky = 0; ky < 5; ky++)
                    #pragma unroll
                    for (int kx = 0; kx < 5; kx++) {
                        float w = wb[ky * 5 + kx];
                        acc[c][0] = fmaf(w, win[ky][kx],         acc[c][0]);
                        acc[c][1] = fmaf(w, win[ky][kx + 1],     acc[c][1]);
                        acc[c][2] = fmaf(w, win[ky + 1][kx],     acc[c][2]);
                        acc[c][3] = fmaf(w, win[ky + 1][kx + 1], acc[c][3]);
                    }
            }
        }
        #pragma unroll
        for (int c = 0; c < 4; c++) {
            int co = cq * 4 + c;
            float m = fmaxf(fmaxf(acc[c][0], acc[c][1]), fmaxf(acc[c][2], acc[c][3]));
            // flatten order: co*25 + py*5 + px  (NCHW reshape)
            h2[g * 400 + co * 25 + p] = fmaxf(m + b2s[co], 0.0f);
        }
    }
    __syncthreads();

    // ---- fc1: [400] -> [120], relu ----
    for (int idx = tid; idx < G * 120; idx += THREADS) {
        int g = idx / 120, j = idx % 120;
        const float* hg = h2 + g * 400;
        float s0 = 0.f, s1 = 0.f, s2 = 0.f, s3 = 0.f;
        #pragma unroll 4
        for (int k = 0; k < 400; k += 4) {
            s0 = fmaf(hg[k],     g_fw1t[(k)     * 120 + j], s0);
            s1 = fmaf(hg[k + 1], g_fw1t[(k + 1) * 120 + j], s1);
            s2 = fmaf(hg[k + 2], g_fw1t[(k + 2) * 120 + j], s2);
            s3 = fmaf(hg[k + 3], g_fw1t[(k + 3) * 120 + j], s3);
        }
        float sum = fb1[j] + ((s0 + s1) + (s2 + s3));
        a1[idx] = fmaxf(sum, 0.0f);
    }
    __syncthreads();

    // ---- fc2: [120] -> [84], relu ----
    for (int idx = tid; idx < G * 84; idx += THREADS) {
        int g = idx / 84, j = idx % 84;
        const float* ag = a1 + g * 120;
        float s0 = 0.f, s1 = 0.f, s2 = 0.f, s3 = 0.f;
        #pragma unroll 4
        for (int k = 0; k < 120; k += 4) {
            s0 = fmaf(ag[k],     g_fw2t[(k)     * 84 + j], s0);
            s1 = fmaf(ag[k + 1], g_fw2t[(k + 1) * 84 + j], s1);
            s2 = fmaf(ag[k + 2], g_fw2t[(k + 2) * 84 + j], s2);
            s3 = fmaf(ag[k + 3], g_fw2t[(k + 3) * 84 + j], s3);
        }
        float sum = fb2[j] + ((s0 + s1) + (s2 + s3));
        a2[idx] = fmaxf(sum, 0.0f);
    }
    __syncthreads();

    // ---- fc3: [84] -> [10] ----
    for (int idx = tid; idx < G * 10; idx += THREADS) {
        int g = idx / 10, j = idx % 10;
        const float* ag = a2 + g * 84;
        float s0 = 0.f, s1 = 0.f;
        #pragma unroll 4
        for (int k = 0; k < 84; k += 2) {
            s0 = fmaf(ag[k],     g_fw3t[(k)     * 10 + j], s0);
            s1 = fmaf(ag[k + 1], g_fw3t[(k + 1) * 10 + j], s1);
        }
        out[(size_t)(img0 + g) * 10 + j] = fb3[j] + s0 + s1;
    }
}

extern "C" void kernel_launch(void* const* d_in, const int* in_sizes, int n_in,
                              void* d_out, int out_size) {
    const float* x   = (const float*)d_in[0];
    const float* w1  = (const float*)d_in[1];
    const float* b1  = (const float*)d_in[2];
    const float* w2  = (const float*)d_in[3];
    const float* b2  = (const float*)d_in[4];
    const float* fw1 = (const float*)d_in[5];
    const float* fb1 = (const float*)d_in[6];
    const float* fw2 = (const float*)d_in[7];
    const float* fb2 = (const float*)d_in[8];
    const float* fw3 = (const float*)d_in[9];
    const float* fb3 = (const float*)d_in[10];
    float* out = (float*)d_out;

    // smem: G*(3072+1176+400+120+84) + 450+2400+6+16 floats = 89,120 bytes
    const int smem_floats = G * (3072 + 1176 + 400 + 120 + 84) + 450 + 2400 + 6 + 16;
    const int smem_bytes = smem_floats * (int)sizeof(float);
    cudaFuncSetAttribute(fused_kernel, cudaFuncAttributeMaxDynamicSharedMemorySize,
                         smem_bytes);

    binarize_kernel<<<5, 256>>>(w1, w2, fw1, fw2, fw3);
    fused_kernel<<<NBLK, THREADS, smem_bytes>>>(x, b1, b2, fb1, fb2, fb3, out);
}

// round 4
// speedup vs baseline: 1.2029x; 1.2029x over previous
#include <cuda_runtime.h>
#include <cuda_bf16.h>

#define G 4
#define THREADS 256
#define NBLK (8192 / G)

// Binarized weights. Conv weights padded: each 5-wide kernel row padded to 8
// floats (pads stay zero from static zero-init) so rows load as float4+float.
__device__ float g_w1p[6 * 3 * 5 * 8];      // [O][I][ky][8]
__device__ float g_w2p[16 * 6 * 5 * 8];     // [O][I][ky][8]
__device__ float g_fw1t[400 * 120];         // [k][j]
__device__ float g_fw2t[120 * 84];          // [k][j]
__device__ float g_fw3t[84 * 10];           // [k][j]

// One block per tensor: scale = mean(|w|), write sign(w)*scale.
__global__ void binarize_kernel(const float* __restrict__ w1,
                                const float* __restrict__ w2,
                                const float* __restrict__ fw1,
                                const float* __restrict__ fw2,
                                const float* __restrict__ fw3) {
    __shared__ float red[256];
    int t = threadIdx.x;
    const float* src = nullptr;
    int n = 0;
    switch (blockIdx.x) {
        case 0: src = w1;  n = 450;   break;
        case 1: src = w2;  n = 2400;  break;
        case 2: src = fw1; n = 48000; break;
        case 3: src = fw2; n = 10080; break;
        case 4: src = fw3; n = 840;   break;
    }
    float s = 0.0f;
    for (int i = t; i < n; i += 256) s += fabsf(src[i]);
    red[t] = s;
    __syncthreads();
    for (int o = 128; o > 0; o >>= 1) {
        if (t < o) red[t] += red[t + o];
        __syncthreads();
    }
    float scale = red[0] / (float)n;

    switch (blockIdx.x) {
        case 0:  // conv1 -> padded [6][3][5][8]
            for (int i = t; i < n; i += 256) {
                int row = i / 5, kx = i % 5;        // row = (o*3+i2)*5+ky
                g_w1p[row * 8 + kx] = (src[i] >= 0.0f) ? scale : -scale;
            }
            break;
        case 1:  // conv2 -> padded [16][6][5][8]
            for (int i = t; i < n; i += 256) {
                int row = i / 5, kx = i % 5;
                g_w2p[row * 8 + kx] = (src[i] >= 0.0f) ? scale : -scale;
            }
            break;
        case 2:  // fc1 [120][400] -> transposed [400][120]
            for (int i = t; i < n; i += 256) {
                int r = i / 400, c = i % 400;
                g_fw1t[c * 120 + r] = (src[i] >= 0.0f) ? scale : -scale;
            }
            break;
        case 3:  // fc2 [84][120] -> [120][84]
            for (int i = t; i < n; i += 256) {
                int r = i / 120, c = i % 120;
                g_fw2t[c * 84 + r] = (src[i] >= 0.0f) ? scale : -scale;
            }
            break;
        case 4:  // fc3 [10][84] -> [84][10]
            for (int i = t; i < n; i += 256) {
                int r = i / 84, c = i % 84;
                g_fw3t[c * 10 + r] = (src[i] >= 0.0f) ? scale : -scale;
            }
            break;
    }
}

extern __shared__ float smem[];

__global__ void __launch_bounds__(THREADS, 3)
fused_kernel(const float* __restrict__ x,
             const float* __restrict__ b1, const float* __restrict__ b2,
             const float* __restrict__ fb1, const float* __restrict__ fb2,
             const float* __restrict__ fb3,
             float* __restrict__ out) {
    // smem partition (floats); p1 first (16B aligned for float2 rows)
    float* const p1  = smem;                  // G*6*14*14 = G*1176
    float* const h2  = p1 + G * 1176;         // G*400
    float* const a1  = h2 + G * 400;          // G*120
    float* const a2  = a1 + G * 120;          // G*84
    float* const w1s = a2 + G * 84;           // 720 (padded)
    float* const w2s = w1s + 720;             // 3840 (padded)
    float* const b1s = w2s + 3840;            // 6
    float* const b2s = b1s + 6;               // 16

    const int tid = threadIdx.x;
    const int img0 = blockIdx.x * G;

    // ---- stage weights+biases into smem ----
    for (int i = tid; i < 720; i += THREADS)  w1s[i] = g_w1p[i];
    for (int i = tid; i < 3840; i += THREADS) w2s[i] = g_w2p[i];
    if (tid < 6)  b1s[tid] = b1[tid];
    if (tid < 16) b2s[tid] = b2[tid];
    __syncthreads();

    // ---- conv1 (3->6, 5x5) + relu + maxpool2 : p1[g][c][14][14] ----
    // Windows read straight from gmem (L1-resident, float2 vectorized).
    for (int s = tid; s < G * 196; s += THREADS) {
        int g = s / 196, p = s % 196;
        int py = p / 14, px = p % 14;
        const float* xg = x + (size_t)(img0 + g) * 3072 + (py * 2) * 32 + px * 2;
        float acc[6][4];
        #pragma unroll
        for (int c = 0; c < 6; c++)
            acc[c][0] = acc[c][1] = acc[c][2] = acc[c][3] = 0.0f;
        #pragma unroll
        for (int cin = 0; cin < 3; cin++) {
            float win[6][6];
            const float2* ib = (const float2*)(xg + cin * 1024);
            #pragma unroll
            for (int r = 0; r < 6; r++) {
                float2 v0 = __ldg(ib + r * 16 + 0);
                float2 v1 = __ldg(ib + r * 16 + 1);
                float2 v2 = __ldg(ib + r * 16 + 2);
                win[r][0] = v0.x; win[r][1] = v0.y;
                win[r][2] = v1.x; win[r][3] = v1.y;
                win[r][4] = v2.x; win[r][5] = v2.y;
            }
            #pragma unroll
            for (int c = 0; c < 6; c++) {
                const float* wb = w1s + (c * 3 + cin) * 40;
                #pragma unroll
                for (int ky = 0; ky < 5; ky++) {
                    float4 wv = *(const float4*)(wb + ky * 8);
                    float w4 = wb[ky * 8 + 4];
                    float wrow[5] = {wv.x, wv.y, wv.z, wv.w, w4};
                    #pragma unroll
                    for (int kx = 0; kx < 5; kx++) {
                        float w = wrow[kx];
                        acc[c][0] = fmaf(w, win[ky][kx],         acc[c][0]);
                        acc[c][1] = fmaf(w, win[ky][kx + 1],     acc[c][1]);
                        acc[c][2] = fmaf(w, win[ky + 1][kx],     acc[c][2]);
                        acc[c][3] = fmaf(w, win[ky + 1][kx + 1], acc[c][3]);
                    }
                }
            }
        }
        #pragma unroll
        for (int c = 0; c < 6; c++) {
            float m = fmaxf(fmaxf(acc[c][0], acc[c][1]), fmaxf(acc[c][2], acc[c][3]));
            p1[(g * 6 + c) * 196 + p] = fmaxf(m + b1s[c], 0.0f);
        }
    }
    __syncthreads();

    // ---- conv2 (6->16, 5x5) + relu + maxpool2 : h2[g][400] ----
    for (int s = tid; s < G * 100; s += THREADS) {
        int g = s / 100, r = s % 100;
        int cq = r / 25, p = r % 25;
        int py = p / 5, px = p % 5;
        const float* inb = p1 + g * 1176 + (py * 2) * 14 + px * 2;
        float acc[4][4];
        #pragma unroll
        for (int c = 0; c < 4; c++)
            acc[c][0] = acc[c][1] = acc[c][2] = acc[c][3] = 0.0f;
        #pragma unroll
        for (int cin = 0; cin < 6; cin++) {
            float win[6][6];
            const float* ib = inb + cin * 196;
            #pragma unroll
            for (int rr = 0; rr < 6; rr++) {
                const float2* row = (const float2*)(ib + rr * 14);
                float2 v0 = row[0];
                float2 v1 = row[1];
                float2 v2 = row[2];
                win[rr][0] = v0.x; win[rr][1] = v0.y;
                win[rr][2] = v1.x; win[rr][3] = v1.y;
                win[rr][4] = v2.x; win[rr][5] = v2.y;
            }
            #pragma unroll
            for (int c = 0; c < 4; c++) {
                int co = cq * 4 + c;
                const float* wb = w2s + (co * 6 + cin) * 40;
                #pragma unroll
                for (int ky = 0; ky < 5; ky++) {
                    float4 wv = *(const float4*)(wb + ky * 8);
                    float w4 = wb[ky * 8 + 4];
                    float wrow[5] = {wv.x, wv.y, wv.z, wv.w, w4};
                    #pragma unroll
                    for (int kx = 0; kx < 5; kx++) {
                        float w = wrow[kx];
                        acc[c][0] = fmaf(w, win[ky][kx],         acc[c][0]);
                        acc[c][1] = fmaf(w, win[ky][kx + 1],     acc[c][1]);
                        acc[c][2] = fmaf(w, win[ky + 1][kx],     acc[c][2]);
                        acc[c][3] = fmaf(w, win[ky + 1][kx + 1], acc[c][3]);
                    }
                }
            }
        }
        #pragma unroll
        for (int c = 0; c < 4; c++) {
            int co = cq * 4 + c;
            float m = fmaxf(fmaxf(acc[c][0], acc[c][1]), fmaxf(acc[c][2], acc[c][3]));
            h2[g * 400 + co * 25 + p] = fmaxf(m + b2s[co], 0.0f);
        }
    }
    __syncthreads();

    // ---- fc1: [400] -> [120], relu. Thread owns j, loops all G images:
    // each weight read once per CTA (L2), activations are smem broadcasts.
    if (tid < 120) {
        int j = tid;
        float acc[G];
        #pragma unroll
        for (int g = 0; g < G; g++) acc[g] = 0.0f;
        for (int k = 0; k < 400; k++) {
            float w = __ldg(g_fw1t + k * 120 + j);
            #pragma unroll
            for (int g = 0; g < G; g++)
                acc[g] = fmaf(w, h2[g * 400 + k], acc[g]);
        }
        float bb = fb1[j];
        #pragma unroll
        for (int g = 0; g < G; g++)
            a1[g * 120 + j] = fmaxf(acc[g] + bb, 0.0f);
    }
    __syncthreads();

    // ---- fc2: [120] -> [84], relu ----
    if (tid < 84) {
        int j = tid;
        float acc[G];
        #pragma unroll
        for (int g = 0; g < G; g++) acc[g] = 0.0f;
        for (int k = 0; k < 120; k++) {
            float w = __ldg(g_fw2t + k * 84 + j);
            #pragma unroll
            for (int g = 0; g < G; g++)
                acc[g] = fmaf(w, a1[g * 120 + k], acc[g]);
        }
        float bb = fb2[j];
        #pragma unroll
        for (int g = 0; g < G; g++)
            a2[g * 84 + j] = fmaxf(acc[g] + bb, 0.0f);
    }
    __syncthreads();

    // ---- fc3: [84] -> [10] ----
    if (tid < G * 10) {
        int g = tid / 10, j = tid % 10;
        const float* ag = a2 + g * 84;
        float s0 = 0.f, s1 = 0.f;
        #pragma unroll 6
        for (int k = 0; k < 84; k += 2) {
            s0 = fmaf(ag[k],     g_fw3t[(k)     * 10 + j], s0);
            s1 = fmaf(ag[k + 1], g_fw3t[(k + 1) * 10 + j], s1);
        }
        out[(size_t)(img0 + g) * 10 + j] = fb3[j] + s0 + s1;
    }
}

extern "C" void kernel_launch(void* const* d_in, const int* in_sizes, int n_in,
                              void* d_out, int out_size) {
    const float* x   = (const float*)d_in[0];
    const float* w1  = (const float*)d_in[1];
    const float* b1  = (const float*)d_in[2];
    const float* w2  = (const float*)d_in[3];
    const float* b2  = (const float*)d_in[4];
    const float* fw1 = (const float*)d_in[5];
    const float* fb1 = (const float*)d_in[6];
    const float* fw2 = (const float*)d_in[7];
    const float* fb2 = (const float*)d_in[8];
    const float* fw3 = (const float*)d_in[9];
    const float* fb3 = (const float*)d_in[10];
    float* out = (float*)d_out;

    // smem: G*(1176+400+120+84) + 720+3840+6+16 floats = 46,808 bytes
    const int smem_floats = G * (1176 + 400 + 120 + 84) + 720 + 3840 + 6 + 16;
    const int smem_bytes = smem_floats * (int)sizeof(float);
    cudaFuncSetAttribute(fused_kernel, cudaFuncAttributeMaxDynamicSharedMemorySize,
                         smem_bytes);

    binarize_kernel<<<5, 256>>>(w1, w2, fw1, fw2, fw3);
    fused_kernel<<<NBLK, THREADS, smem_bytes>>>(x, b1, b2, fb1, fb2, fb3, out);
}

// round 6
// speedup vs baseline: 1.3924x; 1.1575x over previous
#include <cuda_runtime.h>
#include <cuda_bf16.h>

#define G 8
#define THREADS 256
#define NBLK (8192 / G)

// Binarized weights, repacked for vector loads (16B-aligned).
__device__ __align__(16) float g_w1c[3 * 25 * 8];       // [cin][k][c8] (c<6 used)
__device__ __align__(16) float g_w2c[4 * 6 * 25 * 4];   // [cq][cin][k][c4]
__device__ __align__(16) float g_fw1t[400 * 120];       // [k][j]
__device__ __align__(16) float g_fw2t[120 * 84];        // [k][j]
__device__ __align__(16) float g_fw3t[84 * 10];         // [k][j]

__global__ void binarize_kernel(const float* __restrict__ w1,
                                const float* __restrict__ w2,
                                const float* __restrict__ fw1,
                                const float* __restrict__ fw2,
                                const float* __restrict__ fw3) {
    __shared__ float red[256];
    int t = threadIdx.x;
    const float* src = nullptr;
    int n = 0;
    switch (blockIdx.x) {
        case 0: src = w1;  n = 450;   break;
        case 1: src = w2;  n = 2400;  break;
        case 2: src = fw1; n = 48000; break;
        case 3: src = fw2; n = 10080; break;
        case 4: src = fw3; n = 840;   break;
    }
    float s = 0.0f;
    for (int i = t; i < n; i += 256) s += fabsf(src[i]);
    red[t] = s;
    __syncthreads();
    for (int o = 128; o > 0; o >>= 1) {
        if (t < o) red[t] += red[t + o];
        __syncthreads();
    }
    float scale = red[0] / (float)n;

    switch (blockIdx.x) {
        case 0:  // w1[o][cin][5][5] -> [cin][k][c8]
            for (int i = t; i < n; i += 256) {
                int o = i / 75, rem = i % 75, cin = rem / 25, k = rem % 25;
                g_w1c[(cin * 25 + k) * 8 + o] = (src[i] >= 0.0f) ? scale : -scale;
            }
            break;
        case 1:  // w2[o][cin][5][5] -> [cq][cin][k][c4]
            for (int i = t; i < n; i += 256) {
                int o = i / 150, rem = i % 150, cin = rem / 25, k = rem % 25;
                int cq = o >> 2, cl = o & 3;
                g_w2c[((cq * 6 + cin) * 25 + k) * 4 + cl] = (src[i] >= 0.0f) ? scale : -scale;
            }
            break;
        case 2:  // fc1 [120][400] -> [400][120]
            for (int i = t; i < n; i += 256) {
                int r = i / 400, c = i % 400;
                g_fw1t[c * 120 + r] = (src[i] >= 0.0f) ? scale : -scale;
            }
            break;
        case 3:  // fc2 [84][120] -> [120][84]
            for (int i = t; i < n; i += 256) {
                int r = i / 120, c = i % 120;
                g_fw2t[c * 84 + r] = (src[i] >= 0.0f) ? scale : -scale;
            }
            break;
        case 4:  // fc3 [10][84] -> [84][10]
            for (int i = t; i < n; i += 256) {
                int r = i / 84, c = i % 84;
                g_fw3t[c * 10 + r] = (src[i] >= 0.0f) ? scale : -scale;
            }
            break;
    }
}

extern __shared__ float smem[];

__global__ void __launch_bounds__(THREADS, 2)
fused_kernel(const float* __restrict__ x,
             const float* __restrict__ b1, const float* __restrict__ b2,
             const float* __restrict__ fb1, const float* __restrict__ fb2,
             const float* __restrict__ fb3,
             float* __restrict__ out) {
    // smem partition (floats); every segment 16B-aligned.
    float* const p1  = smem;                  // G*1176  [g][c][14*14]
    float* const h2  = p1 + G * 1176;         // G*400
    float* const a1  = h2 + G * 400;          // G*120
    float* const a2  = a1 + G * 120;          // G*84
    float* const w1s = a2 + G * 84;           // 600
    float* const w2s = w1s + 600;             // 2400
    float* const b1s = w2s + 2400;            // 6
    float* const b2s = b1s + 6;               // 16

    const int tid = threadIdx.x;
    const int img0 = blockIdx.x * G;

    for (int i = tid; i < 600; i += THREADS)  w1s[i] = g_w1c[i];
    for (int i = tid; i < 2400; i += THREADS) w2s[i] = g_w2c[i];
    if (tid < 6)  b1s[tid] = b1[tid];
    if (tid < 16) b2s[tid] = b2[tid];
    __syncthreads();

    // ---- conv1 + relu + pool : thread = (g, py, px-pair) -> 1x2 pooled block
    for (int s = tid; s < G * 98; s += THREADS) {
        int g = s / 98, t = s % 98;
        int py = t / 7, pxp = t % 7;
        const float* xg = x + (size_t)(img0 + g) * 3072 + (py * 2) * 32 + pxp * 4;
        float acc[6][2][4];
        #pragma unroll
        for (int c = 0; c < 6; c++)
            #pragma unroll
            for (int r = 0; r < 2; r++)
                acc[c][r][0] = acc[c][r][1] = acc[c][r][2] = acc[c][r][3] = 0.0f;

        #pragma unroll 1
        for (int cin = 0; cin < 3; cin++) {
            float win[6][8];
            const float* ib = xg + cin * 1024;
            #pragma unroll
            for (int r = 0; r < 6; r++) {
                float4 va = __ldg((const float4*)(ib + r * 32));
                float4 vb = __ldg((const float4*)(ib + r * 32 + 4));
                win[r][0] = va.x; win[r][1] = va.y; win[r][2] = va.z; win[r][3] = va.w;
                win[r][4] = vb.x; win[r][5] = vb.y; win[r][6] = vb.z; win[r][7] = vb.w;
            }
            const float* wb = w1s + cin * 200;
            #pragma unroll
            for (int k = 0; k < 25; k++) {
                int ky = k / 5, kx = k % 5;
                float4 w03 = *(const float4*)(wb + k * 8);
                float2 w45 = *(const float2*)(wb + k * 8 + 4);
                float wc[6] = {w03.x, w03.y, w03.z, w03.w, w45.x, w45.y};
                #pragma unroll
                for (int c = 0; c < 6; c++)
                    #pragma unroll
                    for (int r = 0; r < 2; r++)
                        #pragma unroll
                        for (int j = 0; j < 4; j++)
                            acc[c][r][j] = fmaf(wc[c], win[ky + r][kx + j], acc[c][r][j]);
            }
        }
        #pragma unroll
        for (int c = 0; c < 6; c++) {
            float bb = b1s[c];
            float2 v;
            float m0 = fmaxf(fmaxf(acc[c][0][0], acc[c][0][1]),
                             fmaxf(acc[c][1][0], acc[c][1][1]));
            float m1 = fmaxf(fmaxf(acc[c][0][2], acc[c][0][3]),
                             fmaxf(acc[c][1][2], acc[c][1][3]));
            v.x = fmaxf(m0 + bb, 0.0f);
            v.y = fmaxf(m1 + bb, 0.0f);
            *(float2*)(p1 + (g * 6 + c) * 196 + py * 14 + pxp * 2) = v;
        }
    }
    __syncthreads();

    // ---- conv2 + relu + pool : thread = (g, cq, pooled p), 4-channel quad
    for (int s = tid; s < G * 100; s += THREADS) {
        int g = s / 100, r = s % 100;
        int cq = r / 25, p = r % 25;
        int py = p / 5, px = p % 5;
        const float* inb = p1 + g * 1176 + (py * 2) * 14 + px * 2;
        float acc[4][4];
        #pragma unroll
        for (int c = 0; c < 4; c++)
            acc[c][0] = acc[c][1] = acc[c][2] = acc[c][3] = 0.0f;

        #pragma unroll 1
        for (int cin = 0; cin < 6; cin++) {
            float win[6][6];
            const float* ib = inb + cin * 196;
            #pragma unroll
            for (int rr = 0; rr < 6; rr++) {
                const float2* row = (const float2*)(ib + rr * 14);
                float2 v0 = row[0], v1 = row[1], v2 = row[2];
                win[rr][0] = v0.x; win[rr][1] = v0.y;
                win[rr][2] = v1.x; win[rr][3] = v1.y;
                win[rr][4] = v2.x; win[rr][5] = v2.y;
            }
            const float* wb = w2s + (cq * 6 + cin) * 100;
            #pragma unroll
            for (int k = 0; k < 25; k++) {
                int ky = k / 5, kx = k % 5;
                float4 wv = *(const float4*)(wb + k * 4);
                float wc[4] = {wv.x, wv.y, wv.z, wv.w};
                #pragma unroll
                for (int c = 0; c < 4; c++) {
                    acc[c][0] = fmaf(wc[c], win[ky][kx],         acc[c][0]);
                    acc[c][1] = fmaf(wc[c], win[ky][kx + 1],     acc[c][1]);
                    acc[c][2] = fmaf(wc[c], win[ky + 1][kx],     acc[c][2]);
                    acc[c][3] = fmaf(wc[c], win[ky + 1][kx + 1], acc[c][3]);
                }
            }
        }
        #pragma unroll
        for (int c = 0; c < 4; c++) {
            int co = cq * 4 + c;
            float m = fmaxf(fmaxf(acc[c][0], acc[c][1]), fmaxf(acc[c][2], acc[c][3]));
            h2[g * 400 + co * 25 + p] = fmaxf(m + b2s[co], 0.0f);
        }
    }
    __syncthreads();

    // ---- fc1: thread = (j-quad 0..29, image-pair 0..3); float4 both sides
    if (tid < 120) {
        int gpair = tid & 3, jq = tid >> 2;
        int j0 = jq * 4;
        int g0 = gpair * 2, g1 = g0 + 1;
        const float* h0 = h2 + g0 * 400;
        const float* h1 = h2 + g1 * 400;
        float acc0[4] = {0, 0, 0, 0}, acc1[4] = {0, 0, 0, 0};
        for (int k = 0; k < 400; k += 4) {
            float4 ha = *(const float4*)(h0 + k);
            float4 hb = *(const float4*)(h1 + k);
            float av[4] = {ha.x, ha.y, ha.z, ha.w};
            float bv[4] = {hb.x, hb.y, hb.z, hb.w};
            #pragma unroll
            for (int i = 0; i < 4; i++) {
                float4 wv = __ldg((const float4*)(g_fw1t + (k + i) * 120 + j0));
                float wc[4] = {wv.x, wv.y, wv.z, wv.w};
                #pragma unroll
                for (int jj = 0; jj < 4; jj++) {
                    acc0[jj] = fmaf(wc[jj], av[i], acc0[jj]);
                    acc1[jj] = fmaf(wc[jj], bv[i], acc1[jj]);
                }
            }
        }
        float4 r0, r1;
        float bb0 = fb1[j0], bb1 = fb1[j0 + 1], bb2 = fb1[j0 + 2], bb3 = fb1[j0 + 3];
        r0.x = fmaxf(acc0[0] + bb0, 0.0f); r0.y = fmaxf(acc0[1] + bb1, 0.0f);
        r0.z = fmaxf(acc0[2] + bb2, 0.0f); r0.w = fmaxf(acc0[3] + bb3, 0.0f);
        r1.x = fmaxf(acc1[0] + bb0, 0.0f); r1.y = fmaxf(acc1[1] + bb1, 0.0f);
        r1.z = fmaxf(acc1[2] + bb2, 0.0f); r1.w = fmaxf(acc1[3] + bb3, 0.0f);
        *(float4*)(a1 + g0 * 120 + j0) = r0;
        *(float4*)(a1 + g1 * 120 + j0) = r1;
    }
    __syncthreads();

    // ---- fc2: thread = (j-quad 0..20, image-pair 0..3)
    if (tid < 84) {
        int gpair = tid & 3, jq = tid >> 2;
        int j0 = jq * 4;
        int g0 = gpair * 2, g1 = g0 + 1;
        const float* h0 = a1 + g0 * 120;
        const float* h1 = a1 + g1 * 120;
        float acc0[4] = {0, 0, 0, 0}, acc1[4] = {0, 0, 0, 0};
        for (int k = 0; k < 120; k += 4) {
            float4 ha = *(const float4*)(h0 + k);
            float4 hb = *(const float4*)(h1 + k);
            float av[4] = {ha.x, ha.y, ha.z, ha.w};
            float bv[4] = {hb.x, hb.y, hb.z, hb.w};
            #pragma unroll
            for (int i = 0; i < 4; i++) {
                float4 wv = __ldg((const float4*)(g_fw2t + (k + i) * 84 + j0));
                float wc[4] = {wv.x, wv.y, wv.z, wv.w};
                #pragma unroll
                for (int jj = 0; jj < 4; jj++) {
                    acc0[jj] = fmaf(wc[jj], av[i], acc0[jj]);
                    acc1[jj] = fmaf(wc[jj], bv[i], acc1[jj]);
                }
            }
        }
        float4 r0, r1;
        float bb0 = fb2[j0], bb1 = fb2[j0 + 1], bb2v = fb2[j0 + 2], bb3 = fb2[j0 + 3];
        r0.x = fmaxf(acc0[0] + bb0, 0.0f); r0.y = fmaxf(acc0[1] + bb1, 0.0f);
        r0.z = fmaxf(acc0[2] + bb2v, 0.0f); r0.w = fmaxf(acc0[3] + bb3, 0.0f);
        r1.x = fmaxf(acc1[0] + bb0, 0.0f); r1.y = fmaxf(acc1[1] + bb1, 0.0f);
        r1.z = fmaxf(acc1[2] + bb2v, 0.0f); r1.w = fmaxf(acc1[3] + bb3, 0.0f);
        *(float4*)(a2 + g0 * 84 + j0) = r0;
        *(float4*)(a2 + g1 * 84 + j0) = r1;
    }
    __syncthreads();

    // ---- fc3: [84] -> [10]
    if (tid < G * 10) {
        int g = tid / 10, j = tid % 10;
        const float* ag = a2 + g * 84;
        float s0 = 0.f, s1 = 0.f;
        #pragma unroll 6
        for (int k = 0; k < 84; k += 2) {
            s0 = fmaf(ag[k],     g_fw3t[(k)     * 10 + j], s0);
            s1 = fmaf(ag[k + 1], g_fw3t[(k + 1) * 10 + j], s1);
        }
        out[(size_t)(img0 + g) * 10 + j] = fb3[j] + s0 + s1;
    }
}

extern "C" void kernel_launch(void* const* d_in, const int* in_sizes, int n_in,
                              void* d_out, int out_size) {
    const float* x   = (const float*)d_in[0];
    const float* w1  = (const float*)d_in[1];
    const float* b1  = (const float*)d_in[2];
    const float* w2  = (const float*)d_in[3];
    const float* b2  = (const float*)d_in[4];
    const float* fw1 = (const float*)d_in[5];
    const float* fb1 = (const float*)d_in[6];
    const float* fw2 = (const float*)d_in[7];
    const float* fb2 = (const float*)d_in[8];
    const float* fw3 = (const float*)d_in[9];
    const float* fb3 = (const float*)d_in[10];
    float* out = (float*)d_out;

    // smem: G*(1176+400+120+84) + 600+2400+6+16 = 17262 floats = 69,048 B
    const int smem_floats = G * (1176 + 400 + 120 + 84) + 600 + 2400 + 6 + 16;
    const int smem_bytes = smem_floats * (int)sizeof(float);
    cudaFuncSetAttribute(fused_kernel, cudaFuncAttributeMaxDynamicSharedMemorySize,
                         smem_bytes);

    binarize_kernel<<<5, 256>>>(w1, w2, fw1, fw2, fw3);
    fused_kernel<<<NBLK, THREADS, smem_bytes>>>(x, b1, b2, fb1, fb2, fb3, out);
}